// round 14
// baseline (speedup 1.0000x reference)
#include <cuda_runtime.h>
#include <cuda_bf16.h>
#include <cstdint>
#include <cstddef>

#define BB 8
#define TT 512
#define HH 512
#define VV 32000
#define PP 20
#define G4H 2048
#define G4P 80
#define MTOK (BB*TT)   // 4096

// ---------------- scratch (static device globals; no allocations anywhere) ----------------
__device__ float d_xg_enc[MTOK*G4H];
__device__ float d_henc[MTOK*HH];
__device__ float d_hglob[BB*HH];
__device__ float d_cstate[BB*HH];
__device__ float d_xg_pos[MTOK*G4P];
__device__ float d_mu[BB*TT];
__device__ float d_sg[BB*TT];
__device__ float d_gw[(size_t)BB*TT*TT];
__device__ float d_ctx[MTOK*HH];
__device__ __nv_bfloat16 d_A2[(size_t)MTOK*1536];      // A-side split (emb_g, then comb)
__device__ __nv_bfloat16 d_B2[(size_t)VV*1536];        // embedding split (B side)
__device__ __nv_bfloat16 d_W2ih[(size_t)G4H*1536];     // enc_Wih split (B side)
__device__ __nv_bfloat16 d_cat2[(size_t)MTOK*3072];    // cat split (A side)
__device__ __nv_bfloat16 d_Wcat2[(size_t)HH*3072];     // W_cat split (B side)

__device__ __forceinline__ float sigmoidf_(float x) { return 1.f / (1.f + __expf(-x)); }

__device__ __forceinline__ void split_bf16(float a, unsigned short& h, unsigned short& l) {
    __nv_bfloat16 hb = __float2bfloat16_rn(a);
    float lo = a - __bfloat162float(hb);
    __nv_bfloat16 lb = __float2bfloat16_rn(lo);
    h = *reinterpret_cast<unsigned short*>(&hb);
    l = *reinterpret_cast<unsigned short*>(&lb);
}

// ---------------- embedding gather fused with A-side split: d_A2 = [hi|hi|lo] ----------------
__global__ void gather_split_kernel(const int* __restrict__ tokens, const float* __restrict__ emb) {
    int m = blockIdx.x;
    int tok = tokens[m];
    int k4 = threadIdx.x * 4;                 // 128 threads x 4 floats = 512
    float4 v = *reinterpret_cast<const float4*>(emb + (size_t)tok * HH + k4);
    unsigned short h[4], l[4];
    split_bf16(v.x, h[0], l[0]); split_bf16(v.y, h[1], l[1]);
    split_bf16(v.z, h[2], l[2]); split_bf16(v.w, h[3], l[3]);
    ushort4 H  = make_ushort4(h[0], h[1], h[2], h[3]);
    ushort4 Lo = make_ushort4(l[0], l[1], l[2], l[3]);
    __nv_bfloat16* base = d_A2 + (size_t)m * 1536 + k4;
    *reinterpret_cast<ushort4*>(base)        = H;
    *reinterpret_cast<ushort4*>(base + 512)  = H;
    *reinterpret_cast<ushort4*>(base + 1024) = Lo;
}

// ---------------- fp32 SGEMM (small/guarded cases) ----------------
template<int ACT, bool GUARD>
__global__ __launch_bounds__(256) void gemm_nt_kernel(
    const float* __restrict__ A, const float* __restrict__ W,
    const float* __restrict__ b1, const float* __restrict__ b2,
    float* __restrict__ C, int M, int N, int K)
{
    __shared__ float As[8][132];
    __shared__ float Ws[8][132];
    int tid = threadIdx.x;
    int m0 = blockIdx.y * 128, n0 = blockIdx.x * 128;
    int lrow = tid >> 1;
    int lk = (tid & 1) * 4;
    bool a_ok = !GUARD || (m0 + lrow) < M;
    bool w_ok = !GUARD || (n0 + lrow) < N;
    const float* Aptr = A + (size_t)(m0 + lrow) * K + lk;
    const float* Wptr = W + (size_t)(n0 + lrow) * K + lk;
    int tm = (tid >> 4) * 8;
    int tn = (tid & 15) * 8;

    float acc[8][8];
#pragma unroll
    for (int i = 0; i < 8; i++)
#pragma unroll
        for (int j = 0; j < 8; j++) acc[i][j] = 0.f;

    for (int kt = 0; kt < K; kt += 8) {
        float4 av = a_ok ? *reinterpret_cast<const float4*>(Aptr + kt) : make_float4(0,0,0,0);
        float4 wv = w_ok ? *reinterpret_cast<const float4*>(Wptr + kt) : make_float4(0,0,0,0);
        __syncthreads();
        As[lk+0][lrow] = av.x; As[lk+1][lrow] = av.y; As[lk+2][lrow] = av.z; As[lk+3][lrow] = av.w;
        Ws[lk+0][lrow] = wv.x; Ws[lk+1][lrow] = wv.y; Ws[lk+2][lrow] = wv.z; Ws[lk+3][lrow] = wv.w;
        __syncthreads();
#pragma unroll
        for (int k = 0; k < 8; k++) {
            float a[8], b[8];
            *reinterpret_cast<float4*>(&a[0]) = *reinterpret_cast<float4*>(&As[k][tm]);
            *reinterpret_cast<float4*>(&a[4]) = *reinterpret_cast<float4*>(&As[k][tm+4]);
            *reinterpret_cast<float4*>(&b[0]) = *reinterpret_cast<float4*>(&Ws[k][tn]);
            *reinterpret_cast<float4*>(&b[4]) = *reinterpret_cast<float4*>(&Ws[k][tn+4]);
#pragma unroll
            for (int i = 0; i < 8; i++)
#pragma unroll
                for (int j = 0; j < 8; j++) acc[i][j] += a[i] * b[j];
        }
    }

    float bias[8];
#pragma unroll
    for (int j = 0; j < 8; j++) {
        int gn = n0 + tn + j;
        float bv = 0.f;
        if (!GUARD || gn < N) {
            if (b1) bv += b1[gn];
            if (b2) bv += b2[gn];
        }
        bias[j] = bv;
    }

#pragma unroll
    for (int i = 0; i < 8; i++) {
        int gm = m0 + tm + i;
        if (GUARD && gm >= M) continue;
#pragma unroll
        for (int j = 0; j < 8; j++) {
            int gn = n0 + tn + j;
            if (GUARD && gn >= N) continue;
            float v = acc[i][j] + bias[j];
            if (ACT == 1) v = tanhf(v);
            C[(size_t)gm * N + gn] = v;
        }
    }
}

// ---------------- batched fp32 SGEMM: ctx = g @ enc ----------------
__global__ __launch_bounds__(256) void gemm_nn_kernel(
    const float* __restrict__ Ab, const float* __restrict__ Bb, float* __restrict__ Cb,
    int M, int N, int K, size_t sA, size_t sB, size_t sC)
{
    __shared__ float As[8][132];
    __shared__ float Ws[8][132];
    const float* A = Ab + blockIdx.z * sA;
    const float* Bm = Bb + blockIdx.z * sB;
    float* C = Cb + blockIdx.z * sC;
    int tid = threadIdx.x;
    int m0 = blockIdx.y * 128, n0 = blockIdx.x * 128;
    int lrow = tid >> 1;
    int lk = (tid & 1) * 4;
    int bk = tid >> 5;
    int bn = (tid & 31) * 4;
    int tm = (tid >> 4) * 8;
    int tn = (tid & 15) * 8;

    float acc[8][8];
#pragma unroll
    for (int i = 0; i < 8; i++)
#pragma unroll
        for (int j = 0; j < 8; j++) acc[i][j] = 0.f;

    for (int kt = 0; kt < K; kt += 8) {
        float4 av = *reinterpret_cast<const float4*>(A + (size_t)(m0 + lrow) * K + kt + lk);
        float4 bv = *reinterpret_cast<const float4*>(Bm + (size_t)(kt + bk) * N + n0 + bn);
        __syncthreads();
        As[lk+0][lrow] = av.x; As[lk+1][lrow] = av.y; As[lk+2][lrow] = av.z; As[lk+3][lrow] = av.w;
        *reinterpret_cast<float4*>(&Ws[bk][bn]) = bv;
        __syncthreads();
#pragma unroll
        for (int k = 0; k < 8; k++) {
            float a[8], b[8];
            *reinterpret_cast<float4*>(&a[0]) = *reinterpret_cast<float4*>(&As[k][tm]);
            *reinterpret_cast<float4*>(&a[4]) = *reinterpret_cast<float4*>(&As[k][tm+4]);
            *reinterpret_cast<float4*>(&b[0]) = *reinterpret_cast<float4*>(&Ws[k][tn]);
            *reinterpret_cast<float4*>(&b[4]) = *reinterpret_cast<float4*>(&Ws[k][tn+4]);
#pragma unroll
            for (int i = 0; i < 8; i++)
#pragma unroll
                for (int j = 0; j < 8; j++) acc[i][j] += a[i] * b[j];
        }
    }
#pragma unroll
    for (int i = 0; i < 8; i++) {
        float* crow = C + (size_t)(m0 + tm + i) * N + n0 + tn;
#pragma unroll
        for (int j4 = 0; j4 < 2; j4++) {
            float4 v;
            v.x = acc[i][j4*4+0]; v.y = acc[i][j4*4+1];
            v.z = acc[i][j4*4+2]; v.w = acc[i][j4*4+3];
            *reinterpret_cast<float4*>(&crow[j4*4]) = v;
        }
    }
}

// ---------------- encoder LSTM: one launch per timestep (structural floor) ----------------
__global__ void enc_init_kernel() {
    int i = blockIdx.x * blockDim.x + threadIdx.x;
    if (i < BB * HH) { d_hglob[i] = 0.f; d_cstate[i] = 0.f; }
}

__global__ __launch_bounds__(256) void enc_step_kernel(
    int t, const float* __restrict__ xg, const float* __restrict__ Whh)
{
    __shared__ float h_s[BB * HH];
    __shared__ float red_s[16][8];
    int tid = threadIdx.x, cid = blockIdx.x;
    int lane = tid & 31, w = tid >> 5;

    int rl0 = w * 2, rl1 = w * 2 + 1;
    const float* wrow0 = Whh + (size_t)((rl0 >> 2) * HH + cid * 4 + (rl0 & 3)) * HH;
    const float* wrow1 = Whh + (size_t)((rl1 >> 2) * HH + cid * 4 + (rl1 & 3)) * HH;

    float4 wv0[4], wv1[4];
#pragma unroll
    for (int it = 0; it < 4; it++) {
        int k0 = it * 128 + lane * 4;
        wv0[it] = __ldg(reinterpret_cast<const float4*>(wrow0 + k0));
        wv1[it] = __ldg(reinterpret_cast<const float4*>(wrow1 + k0));
    }
    float xgv[4];
    if (tid < 32) {
        int b = tid >> 2, j2 = tid & 3;
#pragma unroll
        for (int q = 0; q < 4; q++)
            xgv[q] = __ldg(&xg[((size_t)(b*TT + t))*G4H + q*HH + cid*4 + j2]);
    }

#pragma unroll
    for (int i = 0; i < 4; i++) {
        int idx = i * 256 + tid;
        reinterpret_cast<float4*>(h_s)[idx] = reinterpret_cast<const float4*>(d_hglob)[idx];
    }
    __syncthreads();

    float acc0[8], acc1[8];
#pragma unroll
    for (int b = 0; b < 8; b++) { acc0[b] = 0.f; acc1[b] = 0.f; }

#pragma unroll
    for (int it = 0; it < 4; it++) {
        int k0 = it * 128 + lane * 4;
        float4 w0 = wv0[it], w1 = wv1[it];
#pragma unroll
        for (int b = 0; b < 8; b++) {
            float4 hv = *reinterpret_cast<const float4*>(&h_s[b * HH + k0]);
            acc0[b] += w0.x*hv.x + w0.y*hv.y + w0.z*hv.z + w0.w*hv.w;
            acc1[b] += w1.x*hv.x + w1.y*hv.y + w1.z*hv.z + w1.w*hv.w;
        }
    }
#pragma unroll
    for (int b = 0; b < 8; b++) {
        float v0 = acc0[b], v1 = acc1[b];
#pragma unroll
        for (int o = 16; o; o >>= 1) {
            v0 += __shfl_xor_sync(0xffffffffu, v0, o);
            v1 += __shfl_xor_sync(0xffffffffu, v1, o);
        }
        if (lane == 0) { red_s[rl0][b] = v0; red_s[rl1][b] = v1; }
    }
    __syncthreads();

    if (tid < 32) {
        int b = tid >> 2, j2 = tid & 3;
        float g4[4];
#pragma unroll
        for (int q = 0; q < 4; q++)
            g4[q] = xgv[q] + red_s[q*4 + j2][b];
        float ii = sigmoidf_(g4[0]);
        float ff = sigmoidf_(g4[1]);
        float gg = tanhf(g4[2]);
        float oo = sigmoidf_(g4[3]);
        int hidx = cid*4 + j2;
        float c = ff * d_cstate[b*HH + hidx] + ii * gg;
        float h = oo * tanhf(c);
        d_cstate[b*HH + hidx] = c;
        d_hglob[b*HH + hidx]  = h;
        d_henc[((size_t)(b*TT + t))*HH + hidx] = h;
    }
}

// ---------------- pos LSTM + heads + mu scan: one CTA per batch ----------------
__global__ __launch_bounds__(128) void pos_kernel(
    const int* __restrict__ pad_len, const float* __restrict__ Whh,
    const float* __restrict__ Wmu, const float* __restrict__ bmu,
    const float* __restrict__ Wsig, const float* __restrict__ bsig)
{
    __shared__ float Whh_s[G4P][PP + 1];
    __shared__ float Wmu_s[3][PP], Wsig_s[PP];
    __shared__ float hp[PP], cpv[PP], gate[G4P];
    __shared__ float head[4];
    __shared__ float bmu_s[3], bsig_s;
    int b = blockIdx.x;
    int tid = threadIdx.x;

    for (int i = tid; i < G4P*PP; i += 128) Whh_s[i / PP][i % PP] = Whh[i];
    for (int i = tid; i < 3*PP;   i += 128) Wmu_s[i / PP][i % PP] = Wmu[i];
    if (tid < PP) { Wsig_s[tid] = Wsig[tid]; hp[tid] = 0.f; cpv[tid] = 0.f; }
    if (tid < 3) bmu_s[tid] = bmu[tid];
    if (tid == 0) bsig_s = bsig[0];
    float L = (float)pad_len[b];
    float mu_prev = 0.f;
    __syncthreads();

    const float* xgb = d_xg_pos + (size_t)b * TT * G4P;
    for (int t = 0; t < TT; t++) {
        if (tid < G4P) {
            float acc = __ldg(&xgb[(size_t)t * G4P + tid]);
            const float* wr = Whh_s[tid];
#pragma unroll
            for (int k = 0; k < PP; k++) acc += wr[k] * hp[k];
            gate[tid] = acc;
        }
        __syncthreads();
        if (tid < PP) {
            float ii = sigmoidf_(gate[tid]);
            float ff = sigmoidf_(gate[PP + tid]);
            float gg = tanhf(gate[2*PP + tid]);
            float oo = sigmoidf_(gate[3*PP + tid]);
            float c = ff * cpv[tid] + ii * gg;
            cpv[tid] = c;
            hp[tid] = oo * tanhf(c);
        }
        __syncthreads();
        if (tid < 4) {
            float s = (tid < 3) ? bmu_s[tid] : bsig_s;
            const float* wv = (tid < 3) ? Wmu_s[tid] : Wsig_s;
#pragma unroll
            for (int p = 0; p < PP; p++) s += hp[p] * wv[p];
            head[tid] = s;
        }
        __syncthreads();
        if (tid == 0) {
            float m0 = fmaxf(head[0], 0.f);
            float m1 = fmaxf(head[1], 0.f);
            float m2 = fmaxf(head[2], 0.f);
            float sgv = sigmoidf_(head[3]);
            float mu = m0*mu_prev + m1/L + m2*((float)(t+1))/L;
            mu = fmaxf(mu, (float)t / L);
            mu_prev = mu;
            d_mu[b*TT + t] = mu;
            d_sg[b*TT + t] = sgv;
        }
        __syncthreads();
    }
}

// ---------------- normalized Gaussian prefix weights ----------------
__global__ void attn_kernel(const int* __restrict__ pad_len) {
    int wq = blockIdx.x * 8 + (threadIdx.x >> 5);
    int lane = threadIdx.x & 31;
    int b = wq >> 9, tq = wq & 511;
    float L = (float)pad_len[b];
    float mu = d_mu[b*TT + tq], sg = d_sg[b*TT + tq];
    float denom = 2.f * sg * sg + 0.001f;
    float* grow = &d_gw[((size_t)(b*TT + tq)) * TT];
    float wv[16];
    float sum = 0.f;
#pragma unroll
    for (int i = 0; i < 16; i++) {
        int tk = lane + i*32;
        float dd = (float)tk / L - mu;
        float v = (tk <= tq) ? __expf(-dd*dd / denom) : 0.f;
        wv[i] = v; sum += v;
    }
#pragma unroll
    for (int o = 16; o; o >>= 1) sum += __shfl_xor_sync(0xffffffffu, sum, o);
    float inv = 1.f / fmaxf(sum, 1e-12f);
#pragma unroll
    for (int i = 0; i < 16; i++) grow[lane + i*32] = wv[i] * inv;
}

// ---------------- fused concat + A-side split: d_cat2 = split([ctx|henc]) ----------------
__global__ void cat_split_kernel() {
    int i = blockIdx.x * blockDim.x + threadIdx.x;     // float4 index over 4096x256
    if (i >= MTOK * 256) return;
    int m = i >> 8, q = i & 255;
    int col4 = q * 4;
    const float* src = (col4 < 512) ? &d_ctx[((size_t)m << 9) + col4]
                                    : &d_henc[((size_t)m << 9) + (col4 - 512)];
    float4 v = *reinterpret_cast<const float4*>(src);
    unsigned short h[4], l[4];
    split_bf16(v.x, h[0], l[0]); split_bf16(v.y, h[1], l[1]);
    split_bf16(v.z, h[2], l[2]); split_bf16(v.w, h[3], l[3]);
    ushort4 H  = make_ushort4(h[0], h[1], h[2], h[3]);
    ushort4 Lo = make_ushort4(l[0], l[1], l[2], l[3]);
    __nv_bfloat16* base = d_cat2 + (size_t)m * 3072 + col4;
    *reinterpret_cast<ushort4*>(base)        = H;
    *reinterpret_cast<ushort4*>(base + 1024) = H;
    *reinterpret_cast<ushort4*>(base + 2048) = Lo;
}

// ---------------- B-side split: Y = [hi | lo | hi] ----------------
__global__ void splitB_kernel(const float* __restrict__ X, __nv_bfloat16* __restrict__ Y, int K0) {
    int K4 = K0 >> 2;
    size_t i = (size_t)blockIdx.x * 256 + threadIdx.x;
    size_t r = i / (size_t)K4;
    int k4 = (int)(i % (size_t)K4) * 4;
    float4 v = *reinterpret_cast<const float4*>(&X[r * (size_t)K0 + k4]);
    unsigned short h[4], l[4];
    split_bf16(v.x, h[0], l[0]); split_bf16(v.y, h[1], l[1]);
    split_bf16(v.z, h[2], l[2]); split_bf16(v.w, h[3], l[3]);
    ushort4 H  = make_ushort4(h[0], h[1], h[2], h[3]);
    ushort4 Lo = make_ushort4(l[0], l[1], l[2], l[3]);
    __nv_bfloat16* base = Y + r * (size_t)(3*K0) + k4;
    *reinterpret_cast<ushort4*>(base)        = H;
    *reinterpret_cast<ushort4*>(base + K0)   = Lo;
    *reinterpret_cast<ushort4*>(base + 2*K0) = H;
}

// ---------------- TC GEMM building blocks ----------------
__device__ __forceinline__ void ldsm_x4(uint32_t& r0, uint32_t& r1, uint32_t& r2, uint32_t& r3,
                                        uint32_t addr) {
    asm volatile("ldmatrix.sync.aligned.m8n8.x4.shared.b16 {%0,%1,%2,%3}, [%4];"
                 : "=r"(r0), "=r"(r1), "=r"(r2), "=r"(r3) : "r"(addr));
}
__device__ __forceinline__ void ldsm_x2(uint32_t& r0, uint32_t& r1, uint32_t addr) {
    asm volatile("ldmatrix.sync.aligned.m8n8.x2.shared.b16 {%0,%1}, [%2];"
                 : "=r"(r0), "=r"(r1) : "r"(addr));
}
__device__ __forceinline__ void mma_bf16(float* c, const uint32_t* a, const uint32_t* b) {
    asm volatile(
        "mma.sync.aligned.m16n8k16.row.col.f32.bf16.bf16.f32 "
        "{%0,%1,%2,%3}, {%4,%5,%6,%7}, {%8,%9}, {%0,%1,%2,%3};"
        : "+f"(c[0]), "+f"(c[1]), "+f"(c[2]), "+f"(c[3])
        : "r"(a[0]), "r"(a[1]), "r"(a[2]), "r"(a[3]), "r"(b[0]), "r"(b[1]));
}
__device__ __forceinline__ void cp_async16(uint32_t s, const void* g) {
    asm volatile("cp.async.cg.shared.global [%0], [%1], 16;" :: "r"(s), "l"(g));
}
#define CP_COMMIT() asm volatile("cp.async.commit_group;" ::: "memory")

// ---------------- unified bf16-split TC GEMM (BM=BN=128, 3-stage) -------------------------
// OUT=0: fp32 C[M,N] with bias/act.  OUT=1: tanh + split-bf16 into d_A2 ([hi|hi|lo], N=512).
#define TCSTG (128*40)
#define TC_SMEM (3 * TCSTG * 2 * 2)

template<int ACT, int OUT>
__global__ __launch_bounds__(256) void tc_gemm_nt(
    const __nv_bfloat16* __restrict__ A, const __nv_bfloat16* __restrict__ B,
    const float* __restrict__ b1, const float* __restrict__ b2,
    float* __restrict__ C, int N, int KDp)
{
    extern __shared__ __align__(16) char smem_raw[];
    __nv_bfloat16* Asm = reinterpret_cast<__nv_bfloat16*>(smem_raw);
    __nv_bfloat16* Bsm = Asm + 3 * TCSTG;

    int tid = threadIdx.x, lane = tid & 31, w = tid >> 5;
    int wm = w >> 2, wn = w & 3;
    int m0 = blockIdx.x * 128, n0 = blockIdx.y * 128;
    int lr = tid >> 2;
    int lc = (tid & 3) * 8;
    const __nv_bfloat16* Ag = A + (size_t)(m0 + lr) * KDp + lc;
    const __nv_bfloat16* Bg = B + (size_t)(n0 + lr) * KDp + lc;

    uint32_t sA = (uint32_t)__cvta_generic_to_shared(Asm);
    uint32_t sB = (uint32_t)__cvta_generic_to_shared(Bsm);
    uint32_t offLo = (uint32_t)(lr * 40 + lc) * 2;
    uint32_t offHi = (uint32_t)((lr + 64) * 40 + lc) * 2;

    int iters = KDp >> 5;

    float acc[4][4][4];
#pragma unroll
    for (int i = 0; i < 4; i++)
#pragma unroll
        for (int j = 0; j < 4; j++) { acc[i][j][0]=0.f; acc[i][j][1]=0.f; acc[i][j][2]=0.f; acc[i][j][3]=0.f; }

#pragma unroll
    for (int s = 0; s < 2; s++) {
        uint32_t sa = sA + (uint32_t)s * TCSTG * 2;
        uint32_t sb = sB + (uint32_t)s * TCSTG * 2;
        cp_async16(sa + offLo, Ag + s * 32);
        cp_async16(sa + offHi, Ag + s * 32 + (size_t)64 * KDp);
        cp_async16(sb + offLo, Bg + s * 32);
        cp_async16(sb + offHi, Bg + s * 32 + (size_t)64 * KDp);
        CP_COMMIT();
    }

    for (int kt = 0; kt < iters; kt++) {
        asm volatile("cp.async.wait_group 1;" ::: "memory");
        __syncthreads();
        int nxt = kt + 2;
        if (nxt < iters) {
            int nb = nxt % 3;
            uint32_t sa = sA + (uint32_t)nb * TCSTG * 2;
            uint32_t sb = sB + (uint32_t)nb * TCSTG * 2;
            cp_async16(sa + offLo, Ag + nxt * 32);
            cp_async16(sa + offHi, Ag + nxt * 32 + (size_t)64 * KDp);
            cp_async16(sb + offLo, Bg + nxt * 32);
            cp_async16(sb + offHi, Bg + nxt * 32 + (size_t)64 * KDp);
        }
        CP_COMMIT();

        int buf = kt % 3;
        uint32_t sAb = sA + (uint32_t)buf * TCSTG * 2;
        uint32_t sBb = sB + (uint32_t)buf * TCSTG * 2;
#pragma unroll
        for (int k16 = 0; k16 < 2; k16++) {
            uint32_t af[4][4], bf[4][2];
#pragma unroll
            for (int mt = 0; mt < 4; mt++) {
                uint32_t addr = sAb + ((wm*64 + mt*16 + (lane & 15)) * 40 + k16*16 + (lane >> 4)*8) * 2;
                ldsm_x4(af[mt][0], af[mt][1], af[mt][2], af[mt][3], addr);
            }
#pragma unroll
            for (int nt = 0; nt < 4; nt++) {
                uint32_t addr = sBb + ((wn*32 + nt*8 + (lane & 7)) * 40 + k16*16 + ((lane >> 3) & 1)*8) * 2;
                ldsm_x2(bf[nt][0], bf[nt][1], addr);
            }
#pragma unroll
            for (int mt = 0; mt < 4; mt++)
#pragma unroll
                for (int nt = 0; nt < 4; nt++)
                    mma_bf16(acc[mt][nt], af[mt], bf[nt]);
        }
    }

#pragma unroll
    for (int mt = 0; mt < 4; mt++) {
        int r0 = m0 + wm*64 + mt*16 + (lane >> 2);
#pragma unroll
        for (int nt = 0; nt < 4; nt++) {
            int cc = n0 + wn*32 + nt*8 + (lane & 3)*2;
            float bb0 = b1[cc],     bb1 = b1[cc + 1];
            if (b2) { bb0 += b2[cc]; bb1 += b2[cc + 1]; }
            float v00 = acc[mt][nt][0] + bb0, v01 = acc[mt][nt][1] + bb1;
            float v10 = acc[mt][nt][2] + bb0, v11 = acc[mt][nt][3] + bb1;
            if (ACT == 1) { v00 = tanhf(v00); v01 = tanhf(v01); v10 = tanhf(v10); v11 = tanhf(v11); }
            if (OUT == 0) {
                *reinterpret_cast<float2*>(&C[(size_t)r0 * N + cc])       = make_float2(v00, v01);
                *reinterpret_cast<float2*>(&C[(size_t)(r0 + 8) * N + cc]) = make_float2(v10, v11);
            } else {
                // split into d_A2: [hi|hi|lo], row stride 1536
                unsigned short h, l;
                __nv_bfloat16* ra = d_A2 + (size_t)r0 * 1536;
                __nv_bfloat16* rb = d_A2 + (size_t)(r0 + 8) * 1536;
                split_bf16(v00, h, l);
                ra[cc] = *(__nv_bfloat16*)&h; ra[cc+512] = *(__nv_bfloat16*)&h; ra[cc+1024] = *(__nv_bfloat16*)&l;
                split_bf16(v01, h, l);
                ra[cc+1] = *(__nv_bfloat16*)&h; ra[cc+513] = *(__nv_bfloat16*)&h; ra[cc+1025] = *(__nv_bfloat16*)&l;
                split_bf16(v10, h, l);
                rb[cc] = *(__nv_bfloat16*)&h; rb[cc+512] = *(__nv_bfloat16*)&h; rb[cc+1024] = *(__nv_bfloat16*)&l;
                split_bf16(v11, h, l);
                rb[cc+1] = *(__nv_bfloat16*)&h; rb[cc+513] = *(__nv_bfloat16*)&h; rb[cc+1025] = *(__nv_bfloat16*)&l;
            }
        }
    }
}

// ---------------- decoder: BM=256, BN=128, 512 threads, 3-stage cp.async -------------------
#define DSTG_A (256*40)
#define DSTG_B (128*40)
#define DEC_SMEM (3 * (DSTG_A + DSTG_B) * 2)

__global__ __launch_bounds__(512) void dec_mma_kernel(
    const __nv_bfloat16* __restrict__ A, const __nv_bfloat16* __restrict__ B,
    const float* __restrict__ bias, float* __restrict__ C)
{
    extern __shared__ __align__(16) char smem_raw[];
    __nv_bfloat16* Asm = reinterpret_cast<__nv_bfloat16*>(smem_raw);            // 3 x 256 x 40
    __nv_bfloat16* Bsm = Asm + 3 * DSTG_A;                                      // 3 x 128 x 40

    const int KDp = 1536, iters = 48;
    int tid = threadIdx.x, lane = tid & 31, w = tid >> 5;   // 16 warps
    int wm = w & 3, wn = w >> 2;                             // 4x4 warp grid
    int m0 = blockIdx.x * 256, n0 = blockIdx.y * 128;

    // loaders: A 2 chunks/thread, B 1 chunk/thread (16B chunks of 8 bf16)
    int ar0 = tid >> 1;                    // rows 0..255
    int ac0 = (tid & 1) * 16;              // col 0 or 16 (two cp at +0,+8)
    int br  = tid >> 2;                    // rows 0..127
    int bc  = (tid & 3) * 8;
    const __nv_bfloat16* Ag = A + (size_t)(m0 + ar0) * KDp + ac0;
    const __nv_bfloat16* Bg = B + (size_t)(n0 + br) * KDp + bc;

    uint32_t sA = (uint32_t)__cvta_generic_to_shared(Asm);
    uint32_t sB = (uint32_t)__cvta_generic_to_shared(Bsm);
    uint32_t aOff0 = (uint32_t)(ar0 * 40 + ac0) * 2;
    uint32_t aOff1 = aOff0 + 16;           // +8 bf16
    uint32_t bOff  = (uint32_t)(br * 40 + bc) * 2;

    float acc[4][4][4];
#pragma unroll
    for (int i = 0; i < 4; i++)
#pragma unroll
        for (int j = 0; j < 4; j++) { acc[i][j][0]=0.f; acc[i][j][1]=0.f; acc[i][j][2]=0.f; acc[i][j][3]=0.f; }

#pragma unroll
    for (int s = 0; s < 2; s++) {
        uint32_t sa = sA + (uint32_t)s * DSTG_A * 2;
        uint32_t sb = sB + (uint32_t)s * DSTG_B * 2;
        cp_async16(sa + aOff0, Ag + s * 32);
        cp_async16(sa + aOff1, Ag + s * 32 + 8);
        cp_async16(sb + bOff,  Bg + s * 32);
        CP_COMMIT();
    }

    for (int kt = 0; kt < iters; kt++) {
        asm volatile("cp.async.wait_group 1;" ::: "memory");
        __syncthreads();
        int nxt = kt + 2;
        if (nxt < iters) {
            int nb = nxt % 3;
            uint32_t sa = sA + (uint32_t)nb * DSTG_A * 2;
            uint32_t sb = sB + (uint32_t)nb * DSTG_B * 2;
            cp_async16(sa + aOff0, Ag + nxt * 32);
            cp_async16(sa + aOff1, Ag + nxt * 32 + 8);
            cp_async16(sb + bOff,  Bg + nxt * 32);
        }
        CP_COMMIT();

        int buf = kt % 3;
        uint32_t sAb = sA + (uint32_t)buf * DSTG_A * 2;
        uint32_t sBb = sB + (uint32_t)buf * DSTG_B * 2;
#pragma unroll
        for (int k16 = 0; k16 < 2; k16++) {
            uint32_t af[4][4], bf[4][2];
#pragma unroll
            for (int mt = 0; mt < 4; mt++) {
                uint32_t addr = sAb + ((wm*64 + mt*16 + (lane & 15)) * 40 + k16*16 + (lane >> 4)*8) * 2;
                ldsm_x4(af[mt][0], af[mt][1], af[mt][2], af[mt][3], addr);
            }
#pragma unroll
            for (int nt = 0; nt < 4; nt++) {
                uint32_t addr = sBb + ((wn*32 + nt*8 + (lane & 7)) * 40 + k16*16 + ((lane >> 3) & 1)*8) * 2;
                ldsm_x2(bf[nt][0], bf[nt][1], addr);
            }
#pragma unroll
            for (int mt = 0; mt < 4; mt++)
#pragma unroll
                for (int nt = 0; nt < 4; nt++)
                    mma_bf16(acc[mt][nt], af[mt], bf[nt]);
        }
    }

#pragma unroll
    for (int mt = 0; mt < 4; mt++) {
        int r0 = m0 + wm*64 + mt*16 + (lane >> 2);
#pragma unroll
        for (int nt = 0; nt < 4; nt++) {
            int cc = n0 + wn*32 + nt*8 + (lane & 3)*2;
            float b0 = bias[cc], b1 = bias[cc + 1];
            *reinterpret_cast<float2*>(&C[(size_t)r0 * VV + cc]) =
                make_float2(acc[mt][nt][0] + b0, acc[mt][nt][1] + b1);
            *reinterpret_cast<float2*>(&C[(size_t)(r0 + 8) * VV + cc]) =
                make_float2(acc[mt][nt][2] + b0, acc[mt][nt][3] + b1);
        }
    }
}

// ---------------- launcher ----------------
extern "C" void kernel_launch(void* const* d_in, const int* in_sizes, int n_in,
                              void* d_out, int out_size)
{
    const int*   tokens   = (const int*)d_in[0];
    const int*   pad_len  = (const int*)d_in[1];
    const float* embedding= (const float*)d_in[2];
    const float* enc_Wih  = (const float*)d_in[3];
    const float* enc_Whh  = (const float*)d_in[4];
    const float* enc_bih  = (const float*)d_in[5];
    const float* enc_bhh  = (const float*)d_in[6];
    const float* pos_Wih  = (const float*)d_in[7];
    const float* pos_Whh  = (const float*)d_in[8];
    const float* pos_bih  = (const float*)d_in[9];
    const float* pos_bhh  = (const float*)d_in[10];
    const float* W_mu     = (const float*)d_in[11];
    const float* b_mu     = (const float*)d_in[12];
    const float* W_sig    = (const float*)d_in[13];
    const float* b_sig    = (const float*)d_in[14];
    const float* W_cat    = (const float*)d_in[15];
    const float* b_cat    = (const float*)d_in[16];
    const float* dec_b    = (const float*)d_in[17];
    float* out = (float*)d_out;

    float *p_xg_enc, *p_henc, *p_xg_pos, *p_gw, *p_ctx;
    __nv_bfloat16 *p_A2, *p_B2, *p_W2ih, *p_cat2, *p_Wcat2;
    cudaGetSymbolAddress((void**)&p_xg_enc, d_xg_enc);
    cudaGetSymbolAddress((void**)&p_henc,   d_henc);
    cudaGetSymbolAddress((void**)&p_xg_pos, d_xg_pos);
    cudaGetSymbolAddress((void**)&p_gw,     d_gw);
    cudaGetSymbolAddress((void**)&p_ctx,    d_ctx);
    cudaGetSymbolAddress((void**)&p_A2,     d_A2);
    cudaGetSymbolAddress((void**)&p_B2,     d_B2);
    cudaGetSymbolAddress((void**)&p_W2ih,   d_W2ih);
    cudaGetSymbolAddress((void**)&p_cat2,   d_cat2);
    cudaGetSymbolAddress((void**)&p_Wcat2,  d_Wcat2);

    cudaFuncSetAttribute(tc_gemm_nt<0,0>, cudaFuncAttributeMaxDynamicSharedMemorySize, TC_SMEM);
    cudaFuncSetAttribute(tc_gemm_nt<1,1>, cudaFuncAttributeMaxDynamicSharedMemorySize, TC_SMEM);
    cudaFuncSetAttribute(dec_mma_kernel, cudaFuncAttributeMaxDynamicSharedMemorySize, DEC_SMEM);

    // 1) gather + A-split; independent B-side splits
    gather_split_kernel<<<MTOK, 128>>>(tokens, embedding);
    splitB_kernel<<<(VV*128)/256, 256>>>(embedding, p_B2, HH);
    splitB_kernel<<<(G4H*128)/256, 256>>>(enc_Wih, p_W2ih, HH);
    splitB_kernel<<<(HH*256)/256, 256>>>(W_cat, p_Wcat2, 2*HH);
    // 2) xg_enc = emb @ Wih^T + bih + bhh  (TC)
    tc_gemm_nt<0,0><<<dim3(MTOK/128, G4H/128), 256, TC_SMEM>>>(
        p_A2, p_W2ih, enc_bih, enc_bhh, p_xg_enc, G4H, 1536);
    // 3) encoder LSTM: init + 512 sequential step launches
    enc_init_kernel<<<(BB*HH + 255)/256, 256>>>();
    for (int t = 0; t < TT; t++)
        enc_step_kernel<<<128, 256>>>(t, p_xg_enc, enc_Whh);
    // 4) xg_pos = henc @ pos_Wih^T + biases (fp32, small N)
    gemm_nt_kernel<0,true><<<dim3(1, MTOK/128), 256>>>(
        p_henc, pos_Wih, pos_bih, pos_bhh, p_xg_pos, MTOK, G4P, HH);
    // 5) pos LSTM + heads + mu scan
    pos_kernel<<<BB, 128>>>(pad_len, pos_Whh, W_mu, b_mu, W_sig, b_sig);
    // 6) attention weights
    attn_kernel<<<(BB*TT)/8, 256>>>(pad_len);
    // 7) ctx = g @ enc
    gemm_nn_kernel<<<dim3(HH/128, TT/128, BB), 256>>>(
        p_gw, p_henc, p_ctx, TT, HH, TT,
        (size_t)TT*TT, (size_t)TT*HH, (size_t)TT*HH);
    // 8) fused concat + A-split
    cat_split_kernel<<<(MTOK*256)/256, 256>>>();
    // 9) comb = tanh(cat @ W_cat^T + b_cat) -> split directly into d_A2 (TC)
    tc_gemm_nt<1,1><<<dim3(MTOK/128, HH/128), 256, TC_SMEM>>>(
        p_cat2, p_Wcat2, b_cat, nullptr, nullptr, HH, 3072);
    // 10) logits = comb @ emb^T + dec_b  (TC, BM=256)
    dec_mma_kernel<<<dim3(MTOK/256, VV/128), 512, DEC_SMEM>>>(p_A2, p_B2, dec_b, out);

    (void)in_sizes; (void)n_in; (void)out_size;
}

// round 15
// speedup vs baseline: 1.0511x; 1.0511x over previous
#include <cuda_runtime.h>
#include <cuda_bf16.h>
#include <cstdint>
#include <cstddef>

#define BB 8
#define TT 512
#define HH 512
#define VV 32000
#define PP 20
#define G4H 2048
#define G4P 80
#define MTOK (BB*TT)   // 4096

// ---------------- scratch (static device globals; no allocations anywhere) ----------------
__device__ float d_xg_enc[MTOK*G4H];
__device__ float d_henc[MTOK*HH];
__device__ float d_hglob[BB*HH];
__device__ float d_cstate[BB*HH];
__device__ float d_xg_pos[MTOK*G4P];
__device__ float d_mu[BB*TT];
__device__ float d_sg[BB*TT];
__device__ float d_gw[(size_t)BB*TT*TT];
__device__ float d_ctx[MTOK*HH];
__device__ float d_comb[MTOK*HH];
__device__ __nv_bfloat16 d_A2[(size_t)MTOK*1536];      // A-side split (emb_g, then comb)
__device__ __nv_bfloat16 d_B2[(size_t)VV*1536];        // embedding split (B side)
__device__ __nv_bfloat16 d_W2ih[(size_t)G4H*1536];     // enc_Wih split (B side)
__device__ __nv_bfloat16 d_cat2[(size_t)MTOK*3072];    // cat split (A side)
__device__ __nv_bfloat16 d_Wcat2[(size_t)HH*3072];     // W_cat split (B side)

__device__ __forceinline__ float sigmoidf_(float x) { return 1.f / (1.f + __expf(-x)); }

__device__ __forceinline__ void split_bf16(float a, unsigned short& h, unsigned short& l) {
    __nv_bfloat16 hb = __float2bfloat16_rn(a);
    float lo = a - __bfloat162float(hb);
    __nv_bfloat16 lb = __float2bfloat16_rn(lo);
    h = *reinterpret_cast<unsigned short*>(&hb);
    l = *reinterpret_cast<unsigned short*>(&lb);
}

// ---------------- embedding gather fused with A-side split: d_A2 = [hi|hi|lo] ----------------
__global__ void gather_split_kernel(const int* __restrict__ tokens, const float* __restrict__ emb) {
    int m = blockIdx.x;
    int tok = tokens[m];
    int k4 = threadIdx.x * 4;                 // 128 threads x 4 floats = 512
    float4 v = *reinterpret_cast<const float4*>(emb + (size_t)tok * HH + k4);
    unsigned short h[4], l[4];
    split_bf16(v.x, h[0], l[0]); split_bf16(v.y, h[1], l[1]);
    split_bf16(v.z, h[2], l[2]); split_bf16(v.w, h[3], l[3]);
    ushort4 H  = make_ushort4(h[0], h[1], h[2], h[3]);
    ushort4 Lo = make_ushort4(l[0], l[1], l[2], l[3]);
    __nv_bfloat16* base = d_A2 + (size_t)m * 1536 + k4;
    *reinterpret_cast<ushort4*>(base)        = H;
    *reinterpret_cast<ushort4*>(base + 512)  = H;
    *reinterpret_cast<ushort4*>(base + 1024) = Lo;
}

// ---------------- fp32 SGEMM (small/guarded cases) ----------------
template<int ACT, bool GUARD>
__global__ __launch_bounds__(256) void gemm_nt_kernel(
    const float* __restrict__ A, const float* __restrict__ W,
    const float* __restrict__ b1, const float* __restrict__ b2,
    float* __restrict__ C, int M, int N, int K)
{
    __shared__ float As[8][132];
    __shared__ float Ws[8][132];
    int tid = threadIdx.x;
    int m0 = blockIdx.y * 128, n0 = blockIdx.x * 128;
    int lrow = tid >> 1;
    int lk = (tid & 1) * 4;
    bool a_ok = !GUARD || (m0 + lrow) < M;
    bool w_ok = !GUARD || (n0 + lrow) < N;
    const float* Aptr = A + (size_t)(m0 + lrow) * K + lk;
    const float* Wptr = W + (size_t)(n0 + lrow) * K + lk;
    int tm = (tid >> 4) * 8;
    int tn = (tid & 15) * 8;

    float acc[8][8];
#pragma unroll
    for (int i = 0; i < 8; i++)
#pragma unroll
        for (int j = 0; j < 8; j++) acc[i][j] = 0.f;

    for (int kt = 0; kt < K; kt += 8) {
        float4 av = a_ok ? *reinterpret_cast<const float4*>(Aptr + kt) : make_float4(0,0,0,0);
        float4 wv = w_ok ? *reinterpret_cast<const float4*>(Wptr + kt) : make_float4(0,0,0,0);
        __syncthreads();
        As[lk+0][lrow] = av.x; As[lk+1][lrow] = av.y; As[lk+2][lrow] = av.z; As[lk+3][lrow] = av.w;
        Ws[lk+0][lrow] = wv.x; Ws[lk+1][lrow] = wv.y; Ws[lk+2][lrow] = wv.z; Ws[lk+3][lrow] = wv.w;
        __syncthreads();
#pragma unroll
        for (int k = 0; k < 8; k++) {
            float a[8], b[8];
            *reinterpret_cast<float4*>(&a[0]) = *reinterpret_cast<float4*>(&As[k][tm]);
            *reinterpret_cast<float4*>(&a[4]) = *reinterpret_cast<float4*>(&As[k][tm+4]);
            *reinterpret_cast<float4*>(&b[0]) = *reinterpret_cast<float4*>(&Ws[k][tn]);
            *reinterpret_cast<float4*>(&b[4]) = *reinterpret_cast<float4*>(&Ws[k][tn+4]);
#pragma unroll
            for (int i = 0; i < 8; i++)
#pragma unroll
                for (int j = 0; j < 8; j++) acc[i][j] += a[i] * b[j];
        }
    }

    float bias[8];
#pragma unroll
    for (int j = 0; j < 8; j++) {
        int gn = n0 + tn + j;
        float bv = 0.f;
        if (!GUARD || gn < N) {
            if (b1) bv += b1[gn];
            if (b2) bv += b2[gn];
        }
        bias[j] = bv;
    }

#pragma unroll
    for (int i = 0; i < 8; i++) {
        int gm = m0 + tm + i;
        if (GUARD && gm >= M) continue;
#pragma unroll
        for (int j = 0; j < 8; j++) {
            int gn = n0 + tn + j;
            if (GUARD && gn >= N) continue;
            float v = acc[i][j] + bias[j];
            if (ACT == 1) v = tanhf(v);
            C[(size_t)gm * N + gn] = v;
        }
    }
}

// ---------------- batched fp32 SGEMM: ctx = g @ enc ----------------
__global__ __launch_bounds__(256) void gemm_nn_kernel(
    const float* __restrict__ Ab, const float* __restrict__ Bb, float* __restrict__ Cb,
    int M, int N, int K, size_t sA, size_t sB, size_t sC)
{
    __shared__ float As[8][132];
    __shared__ float Ws[8][132];
    const float* A = Ab + blockIdx.z * sA;
    const float* Bm = Bb + blockIdx.z * sB;
    float* C = Cb + blockIdx.z * sC;
    int tid = threadIdx.x;
    int m0 = blockIdx.y * 128, n0 = blockIdx.x * 128;
    int lrow = tid >> 1;
    int lk = (tid & 1) * 4;
    int bk = tid >> 5;
    int bn = (tid & 31) * 4;
    int tm = (tid >> 4) * 8;
    int tn = (tid & 15) * 8;

    float acc[8][8];
#pragma unroll
    for (int i = 0; i < 8; i++)
#pragma unroll
        for (int j = 0; j < 8; j++) acc[i][j] = 0.f;

    for (int kt = 0; kt < K; kt += 8) {
        float4 av = *reinterpret_cast<const float4*>(A + (size_t)(m0 + lrow) * K + kt + lk);
        float4 bv = *reinterpret_cast<const float4*>(Bm + (size_t)(kt + bk) * N + n0 + bn);
        __syncthreads();
        As[lk+0][lrow] = av.x; As[lk+1][lrow] = av.y; As[lk+2][lrow] = av.z; As[lk+3][lrow] = av.w;
        *reinterpret_cast<float4*>(&Ws[bk][bn]) = bv;
        __syncthreads();
#pragma unroll
        for (int k = 0; k < 8; k++) {
            float a[8], b[8];
            *reinterpret_cast<float4*>(&a[0]) = *reinterpret_cast<float4*>(&As[k][tm]);
            *reinterpret_cast<float4*>(&a[4]) = *reinterpret_cast<float4*>(&As[k][tm+4]);
            *reinterpret_cast<float4*>(&b[0]) = *reinterpret_cast<float4*>(&Ws[k][tn]);
            *reinterpret_cast<float4*>(&b[4]) = *reinterpret_cast<float4*>(&Ws[k][tn+4]);
#pragma unroll
            for (int i = 0; i < 8; i++)
#pragma unroll
                for (int j = 0; j < 8; j++) acc[i][j] += a[i] * b[j];
        }
    }
#pragma unroll
    for (int i = 0; i < 8; i++) {
        float* crow = C + (size_t)(m0 + tm + i) * N + n0 + tn;
#pragma unroll
        for (int j4 = 0; j4 < 2; j4++) {
            float4 v;
            v.x = acc[i][j4*4+0]; v.y = acc[i][j4*4+1];
            v.z = acc[i][j4*4+2]; v.w = acc[i][j4*4+3];
            *reinterpret_cast<float4*>(&crow[j4*4]) = v;
        }
    }
}

// ---------------- encoder LSTM: one launch per timestep (structural floor) ----------------
__global__ void enc_init_kernel() {
    int i = blockIdx.x * blockDim.x + threadIdx.x;
    if (i < BB * HH) { d_hglob[i] = 0.f; d_cstate[i] = 0.f; }
}

__global__ __launch_bounds__(256) void enc_step_kernel(
    int t, const float* __restrict__ xg, const float* __restrict__ Whh)
{
    __shared__ float h_s[BB * HH];
    __shared__ float red_s[16][8];
    int tid = threadIdx.x, cid = blockIdx.x;
    int lane = tid & 31, w = tid >> 5;

    int rl0 = w * 2, rl1 = w * 2 + 1;
    const float* wrow0 = Whh + (size_t)((rl0 >> 2) * HH + cid * 4 + (rl0 & 3)) * HH;
    const float* wrow1 = Whh + (size_t)((rl1 >> 2) * HH + cid * 4 + (rl1 & 3)) * HH;

    float4 wv0[4], wv1[4];
#pragma unroll
    for (int it = 0; it < 4; it++) {
        int k0 = it * 128 + lane * 4;
        wv0[it] = __ldg(reinterpret_cast<const float4*>(wrow0 + k0));
        wv1[it] = __ldg(reinterpret_cast<const float4*>(wrow1 + k0));
    }
    float xgv[4];
    if (tid < 32) {
        int b = tid >> 2, j2 = tid & 3;
#pragma unroll
        for (int q = 0; q < 4; q++)
            xgv[q] = __ldg(&xg[((size_t)(b*TT + t))*G4H + q*HH + cid*4 + j2]);
    }

#pragma unroll
    for (int i = 0; i < 4; i++) {
        int idx = i * 256 + tid;
        reinterpret_cast<float4*>(h_s)[idx] = reinterpret_cast<const float4*>(d_hglob)[idx];
    }
    __syncthreads();

    float acc0[8], acc1[8];
#pragma unroll
    for (int b = 0; b < 8; b++) { acc0[b] = 0.f; acc1[b] = 0.f; }

#pragma unroll
    for (int it = 0; it < 4; it++) {
        int k0 = it * 128 + lane * 4;
        float4 w0 = wv0[it], w1 = wv1[it];
#pragma unroll
        for (int b = 0; b < 8; b++) {
            float4 hv = *reinterpret_cast<const float4*>(&h_s[b * HH + k0]);
            acc0[b] += w0.x*hv.x + w0.y*hv.y + w0.z*hv.z + w0.w*hv.w;
            acc1[b] += w1.x*hv.x + w1.y*hv.y + w1.z*hv.z + w1.w*hv.w;
        }
    }
#pragma unroll
    for (int b = 0; b < 8; b++) {
        float v0 = acc0[b], v1 = acc1[b];
#pragma unroll
        for (int o = 16; o; o >>= 1) {
            v0 += __shfl_xor_sync(0xffffffffu, v0, o);
            v1 += __shfl_xor_sync(0xffffffffu, v1, o);
        }
        if (lane == 0) { red_s[rl0][b] = v0; red_s[rl1][b] = v1; }
    }
    __syncthreads();

    if (tid < 32) {
        int b = tid >> 2, j2 = tid & 3;
        float g4[4];
#pragma unroll
        for (int q = 0; q < 4; q++)
            g4[q] = xgv[q] + red_s[q*4 + j2][b];
        float ii = sigmoidf_(g4[0]);
        float ff = sigmoidf_(g4[1]);
        float gg = tanhf(g4[2]);
        float oo = sigmoidf_(g4[3]);
        int hidx = cid*4 + j2;
        float c = ff * d_cstate[b*HH + hidx] + ii * gg;
        float h = oo * tanhf(c);
        d_cstate[b*HH + hidx] = c;
        d_hglob[b*HH + hidx]  = h;
        d_henc[((size_t)(b*TT + t))*HH + hidx] = h;
    }
}

// ---------------- pos LSTM + heads + mu scan: one CTA per batch ----------------
__global__ __launch_bounds__(128) void pos_kernel(
    const int* __restrict__ pad_len, const float* __restrict__ Whh,
    const float* __restrict__ Wmu, const float* __restrict__ bmu,
    const float* __restrict__ Wsig, const float* __restrict__ bsig)
{
    __shared__ float Whh_s[G4P][PP + 1];
    __shared__ float Wmu_s[3][PP], Wsig_s[PP];
    __shared__ float hp[PP], cpv[PP], gate[G4P];
    __shared__ float head[4];
    __shared__ float bmu_s[3], bsig_s;
    int b = blockIdx.x;
    int tid = threadIdx.x;

    for (int i = tid; i < G4P*PP; i += 128) Whh_s[i / PP][i % PP] = Whh[i];
    for (int i = tid; i < 3*PP;   i += 128) Wmu_s[i / PP][i % PP] = Wmu[i];
    if (tid < PP) { Wsig_s[tid] = Wsig[tid]; hp[tid] = 0.f; cpv[tid] = 0.f; }
    if (tid < 3) bmu_s[tid] = bmu[tid];
    if (tid == 0) bsig_s = bsig[0];
    float L = (float)pad_len[b];
    float mu_prev = 0.f;
    __syncthreads();

    const float* xgb = d_xg_pos + (size_t)b * TT * G4P;
    for (int t = 0; t < TT; t++) {
        if (tid < G4P) {
            float acc = __ldg(&xgb[(size_t)t * G4P + tid]);
            const float* wr = Whh_s[tid];
#pragma unroll
            for (int k = 0; k < PP; k++) acc += wr[k] * hp[k];
            gate[tid] = acc;
        }
        __syncthreads();
        if (tid < PP) {
            float ii = sigmoidf_(gate[tid]);
            float ff = sigmoidf_(gate[PP + tid]);
            float gg = tanhf(gate[2*PP + tid]);
            float oo = sigmoidf_(gate[3*PP + tid]);
            float c = ff * cpv[tid] + ii * gg;
            cpv[tid] = c;
            hp[tid] = oo * tanhf(c);
        }
        __syncthreads();
        if (tid < 4) {
            float s = (tid < 3) ? bmu_s[tid] : bsig_s;
            const float* wv = (tid < 3) ? Wmu_s[tid] : Wsig_s;
#pragma unroll
            for (int p = 0; p < PP; p++) s += hp[p] * wv[p];
            head[tid] = s;
        }
        __syncthreads();
        if (tid == 0) {
            float m0 = fmaxf(head[0], 0.f);
            float m1 = fmaxf(head[1], 0.f);
            float m2 = fmaxf(head[2], 0.f);
            float sgv = sigmoidf_(head[3]);
            float mu = m0*mu_prev + m1/L + m2*((float)(t+1))/L;
            mu = fmaxf(mu, (float)t / L);
            mu_prev = mu;
            d_mu[b*TT + t] = mu;
            d_sg[b*TT + t] = sgv;
        }
        __syncthreads();
    }
}

// ---------------- normalized Gaussian prefix weights ----------------
__global__ void attn_kernel(const int* __restrict__ pad_len) {
    int wq = blockIdx.x * 8 + (threadIdx.x >> 5);
    int lane = threadIdx.x & 31;
    int b = wq >> 9, tq = wq & 511;
    float L = (float)pad_len[b];
    float mu = d_mu[b*TT + tq], sg = d_sg[b*TT + tq];
    float denom = 2.f * sg * sg + 0.001f;
    float* grow = &d_gw[((size_t)(b*TT + tq)) * TT];
    float wv[16];
    float sum = 0.f;
#pragma unroll
    for (int i = 0; i < 16; i++) {
        int tk = lane + i*32;
        float dd = (float)tk / L - mu;
        float v = (tk <= tq) ? __expf(-dd*dd / denom) : 0.f;
        wv[i] = v; sum += v;
    }
#pragma unroll
    for (int o = 16; o; o >>= 1) sum += __shfl_xor_sync(0xffffffffu, sum, o);
    float inv = 1.f / fmaxf(sum, 1e-12f);
#pragma unroll
    for (int i = 0; i < 16; i++) grow[lane + i*32] = wv[i] * inv;
}

// ---------------- fused concat + A-side split: d_cat2 = split([ctx|henc]) ----------------
__global__ void cat_split_kernel() {
    int i = blockIdx.x * blockDim.x + threadIdx.x;     // float4 index over 4096x256
    if (i >= MTOK * 256) return;
    int m = i >> 8, q = i & 255;
    int col4 = q * 4;
    const float* src = (col4 < 512) ? &d_ctx[((size_t)m << 9) + col4]
                                    : &d_henc[((size_t)m << 9) + (col4 - 512)];
    float4 v = *reinterpret_cast<const float4*>(src);
    unsigned short h[4], l[4];
    split_bf16(v.x, h[0], l[0]); split_bf16(v.y, h[1], l[1]);
    split_bf16(v.z, h[2], l[2]); split_bf16(v.w, h[3], l[3]);
    ushort4 H  = make_ushort4(h[0], h[1], h[2], h[3]);
    ushort4 Lo = make_ushort4(l[0], l[1], l[2], l[3]);
    __nv_bfloat16* base = d_cat2 + (size_t)m * 3072 + col4;
    *reinterpret_cast<ushort4*>(base)        = H;
    *reinterpret_cast<ushort4*>(base + 1024) = H;
    *reinterpret_cast<ushort4*>(base + 2048) = Lo;
}

// ---------------- A-side split (comb): Y = [hi | hi | lo] ----------------
__global__ void splitA_kernel(const float* __restrict__ X, __nv_bfloat16* __restrict__ Y, int K0) {
    int K4 = K0 >> 2;
    size_t i = (size_t)blockIdx.x * 256 + threadIdx.x;
    size_t r = i / (size_t)K4;
    int k4 = (int)(i % (size_t)K4) * 4;
    float4 v = *reinterpret_cast<const float4*>(&X[r * (size_t)K0 + k4]);
    unsigned short h[4], l[4];
    split_bf16(v.x, h[0], l[0]); split_bf16(v.y, h[1], l[1]);
    split_bf16(v.z, h[2], l[2]); split_bf16(v.w, h[3], l[3]);
    ushort4 H  = make_ushort4(h[0], h[1], h[2], h[3]);
    ushort4 Lo = make_ushort4(l[0], l[1], l[2], l[3]);
    __nv_bfloat16* base = Y + r * (size_t)(3*K0) + k4;
    *reinterpret_cast<ushort4*>(base)        = H;
    *reinterpret_cast<ushort4*>(base + K0)   = H;
    *reinterpret_cast<ushort4*>(base + 2*K0) = Lo;
}

// ---------------- B-side split: Y = [hi | lo | hi] ----------------
__global__ void splitB_kernel(const float* __restrict__ X, __nv_bfloat16* __restrict__ Y, int K0) {
    int K4 = K0 >> 2;
    size_t i = (size_t)blockIdx.x * 256 + threadIdx.x;
    size_t r = i / (size_t)K4;
    int k4 = (int)(i % (size_t)K4) * 4;
    float4 v = *reinterpret_cast<const float4*>(&X[r * (size_t)K0 + k4]);
    unsigned short h[4], l[4];
    split_bf16(v.x, h[0], l[0]); split_bf16(v.y, h[1], l[1]);
    split_bf16(v.z, h[2], l[2]); split_bf16(v.w, h[3], l[3]);
    ushort4 H  = make_ushort4(h[0], h[1], h[2], h[3]);
    ushort4 Lo = make_ushort4(l[0], l[1], l[2], l[3]);
    __nv_bfloat16* base = Y + r * (size_t)(3*K0) + k4;
    *reinterpret_cast<ushort4*>(base)        = H;
    *reinterpret_cast<ushort4*>(base + K0)   = Lo;
    *reinterpret_cast<ushort4*>(base + 2*K0) = H;
}

// ---------------- TC GEMM building blocks ----------------
__device__ __forceinline__ void ldsm_x4(uint32_t& r0, uint32_t& r1, uint32_t& r2, uint32_t& r3,
                                        uint32_t addr) {
    asm volatile("ldmatrix.sync.aligned.m8n8.x4.shared.b16 {%0,%1,%2,%3}, [%4];"
                 : "=r"(r0), "=r"(r1), "=r"(r2), "=r"(r3) : "r"(addr));
}
__device__ __forceinline__ void ldsm_x2(uint32_t& r0, uint32_t& r1, uint32_t addr) {
    asm volatile("ldmatrix.sync.aligned.m8n8.x2.shared.b16 {%0,%1}, [%2];"
                 : "=r"(r0), "=r"(r1) : "r"(addr));
}
__device__ __forceinline__ void mma_bf16(float* c, const uint32_t* a, const uint32_t* b) {
    asm volatile(
        "mma.sync.aligned.m16n8k16.row.col.f32.bf16.bf16.f32 "
        "{%0,%1,%2,%3}, {%4,%5,%6,%7}, {%8,%9}, {%0,%1,%2,%3};"
        : "+f"(c[0]), "+f"(c[1]), "+f"(c[2]), "+f"(c[3])
        : "r"(a[0]), "r"(a[1]), "r"(a[2]), "r"(a[3]), "r"(b[0]), "r"(b[1]));
}
__device__ __forceinline__ void cp_async16(uint32_t s, const void* g) {
    asm volatile("cp.async.cg.shared.global [%0], [%1], 16;" :: "r"(s), "l"(g));
}
#define CP_COMMIT() asm volatile("cp.async.commit_group;" ::: "memory")

// ---------------- unified bf16-split TC GEMM (BM=BN=128, 3-stage cp.async) -----------------
#define TCSTG (128*40)
#define TC_SMEM (3 * TCSTG * 2 * 2)

template<int ACT>
__global__ __launch_bounds__(256) void tc_gemm_nt(
    const __nv_bfloat16* __restrict__ A, const __nv_bfloat16* __restrict__ B,
    const float* __restrict__ b1, const float* __restrict__ b2,
    float* __restrict__ C, int N, int KDp)
{
    extern __shared__ __align__(16) char smem_raw[];
    __nv_bfloat16* Asm = reinterpret_cast<__nv_bfloat16*>(smem_raw);
    __nv_bfloat16* Bsm = Asm + 3 * TCSTG;

    int tid = threadIdx.x, lane = tid & 31, w = tid >> 5;
    int wm = w >> 2, wn = w & 3;
    int m0 = blockIdx.x * 128, n0 = blockIdx.y * 128;
    int lr = tid >> 2;
    int lc = (tid & 3) * 8;
    const __nv_bfloat16* Ag = A + (size_t)(m0 + lr) * KDp + lc;
    const __nv_bfloat16* Bg = B + (size_t)(n0 + lr) * KDp + lc;

    uint32_t sA = (uint32_t)__cvta_generic_to_shared(Asm);
    uint32_t sB = (uint32_t)__cvta_generic_to_shared(Bsm);
    uint32_t offLo = (uint32_t)(lr * 40 + lc) * 2;
    uint32_t offHi = (uint32_t)((lr + 64) * 40 + lc) * 2;

    int iters = KDp >> 5;

    float acc[4][4][4];
#pragma unroll
    for (int i = 0; i < 4; i++)
#pragma unroll
        for (int j = 0; j < 4; j++) { acc[i][j][0]=0.f; acc[i][j][1]=0.f; acc[i][j][2]=0.f; acc[i][j][3]=0.f; }

#pragma unroll
    for (int s = 0; s < 2; s++) {
        uint32_t sa = sA + (uint32_t)s * TCSTG * 2;
        uint32_t sb = sB + (uint32_t)s * TCSTG * 2;
        cp_async16(sa + offLo, Ag + s * 32);
        cp_async16(sa + offHi, Ag + s * 32 + (size_t)64 * KDp);
        cp_async16(sb + offLo, Bg + s * 32);
        cp_async16(sb + offHi, Bg + s * 32 + (size_t)64 * KDp);
        CP_COMMIT();
    }

    for (int kt = 0; kt < iters; kt++) {
        asm volatile("cp.async.wait_group 1;" ::: "memory");
        __syncthreads();
        int nxt = kt + 2;
        if (nxt < iters) {
            int nb = nxt % 3;
            uint32_t sa = sA + (uint32_t)nb * TCSTG * 2;
            uint32_t sb = sB + (uint32_t)nb * TCSTG * 2;
            cp_async16(sa + offLo, Ag + nxt * 32);
            cp_async16(sa + offHi, Ag + nxt * 32 + (size_t)64 * KDp);
            cp_async16(sb + offLo, Bg + nxt * 32);
            cp_async16(sb + offHi, Bg + nxt * 32 + (size_t)64 * KDp);
        }
        CP_COMMIT();

        int buf = kt % 3;
        uint32_t sAb = sA + (uint32_t)buf * TCSTG * 2;
        uint32_t sBb = sB + (uint32_t)buf * TCSTG * 2;
#pragma unroll
        for (int k16 = 0; k16 < 2; k16++) {
            uint32_t af[4][4], bf[4][2];
#pragma unroll
            for (int mt = 0; mt < 4; mt++) {
                uint32_t addr = sAb + ((wm*64 + mt*16 + (lane & 15)) * 40 + k16*16 + (lane >> 4)*8) * 2;
                ldsm_x4(af[mt][0], af[mt][1], af[mt][2], af[mt][3], addr);
            }
#pragma unroll
            for (int nt = 0; nt < 4; nt++) {
                uint32_t addr = sBb + ((wn*32 + nt*8 + (lane & 7)) * 40 + k16*16 + ((lane >> 3) & 1)*8) * 2;
                ldsm_x2(bf[nt][0], bf[nt][1], addr);
            }
#pragma unroll
            for (int mt = 0; mt < 4; mt++)
#pragma unroll
                for (int nt = 0; nt < 4; nt++)
                    mma_bf16(acc[mt][nt], af[mt], bf[nt]);
        }
    }

#pragma unroll
    for (int mt = 0; mt < 4; mt++) {
        int r0 = m0 + wm*64 + mt*16 + (lane >> 2);
#pragma unroll
        for (int nt = 0; nt < 4; nt++) {
            int cc = n0 + wn*32 + nt*8 + (lane & 3)*2;
            float bb0 = b1[cc],     bb1 = b1[cc + 1];
            if (b2) { bb0 += b2[cc]; bb1 += b2[cc + 1]; }
            float v00 = acc[mt][nt][0] + bb0, v01 = acc[mt][nt][1] + bb1;
            float v10 = acc[mt][nt][2] + bb0, v11 = acc[mt][nt][3] + bb1;
            if (ACT == 1) { v00 = tanhf(v00); v01 = tanhf(v01); v10 = tanhf(v10); v11 = tanhf(v11); }
            *reinterpret_cast<float2*>(&C[(size_t)r0 * N + cc])       = make_float2(v00, v01);
            *reinterpret_cast<float2*>(&C[(size_t)(r0 + 8) * N + cc]) = make_float2(v10, v11);
        }
    }
}

// ---------------- launcher ----------------
extern "C" void kernel_launch(void* const* d_in, const int* in_sizes, int n_in,
                              void* d_out, int out_size)
{
    const int*   tokens   = (const int*)d_in[0];
    const int*   pad_len  = (const int*)d_in[1];
    const float* embedding= (const float*)d_in[2];
    const float* enc_Wih  = (const float*)d_in[3];
    const float* enc_Whh  = (const float*)d_in[4];
    const float* enc_bih  = (const float*)d_in[5];
    const float* enc_bhh  = (const float*)d_in[6];
    const float* pos_Wih  = (const float*)d_in[7];
    const float* pos_Whh  = (const float*)d_in[8];
    const float* pos_bih  = (const float*)d_in[9];
    const float* pos_bhh  = (const float*)d_in[10];
    const float* W_mu     = (const float*)d_in[11];
    const float* b_mu     = (const float*)d_in[12];
    const float* W_sig    = (const float*)d_in[13];
    const float* b_sig    = (const float*)d_in[14];
    const float* W_cat    = (const float*)d_in[15];
    const float* b_cat    = (const float*)d_in[16];
    const float* dec_b    = (const float*)d_in[17];
    float* out = (float*)d_out;

    float *p_xg_enc, *p_henc, *p_xg_pos, *p_gw, *p_ctx, *p_comb;
    __nv_bfloat16 *p_A2, *p_B2, *p_W2ih, *p_cat2, *p_Wcat2;
    cudaGetSymbolAddress((void**)&p_xg_enc, d_xg_enc);
    cudaGetSymbolAddress((void**)&p_henc,   d_henc);
    cudaGetSymbolAddress((void**)&p_xg_pos, d_xg_pos);
    cudaGetSymbolAddress((void**)&p_gw,     d_gw);
    cudaGetSymbolAddress((void**)&p_ctx,    d_ctx);
    cudaGetSymbolAddress((void**)&p_comb,   d_comb);
    cudaGetSymbolAddress((void**)&p_A2,     d_A2);
    cudaGetSymbolAddress((void**)&p_B2,     d_B2);
    cudaGetSymbolAddress((void**)&p_W2ih,   d_W2ih);
    cudaGetSymbolAddress((void**)&p_cat2,   d_cat2);
    cudaGetSymbolAddress((void**)&p_Wcat2,  d_Wcat2);

    cudaFuncSetAttribute(tc_gemm_nt<0>, cudaFuncAttributeMaxDynamicSharedMemorySize, TC_SMEM);
    cudaFuncSetAttribute(tc_gemm_nt<1>, cudaFuncAttributeMaxDynamicSharedMemorySize, TC_SMEM);

    // 1) gather + A-split; independent B-side splits
    gather_split_kernel<<<MTOK, 128>>>(tokens, embedding);
    splitB_kernel<<<(VV*128)/256, 256>>>(embedding, p_B2, HH);
    splitB_kernel<<<(G4H*128)/256, 256>>>(enc_Wih, p_W2ih, HH);
    splitB_kernel<<<(HH*256)/256, 256>>>(W_cat, p_Wcat2, 2*HH);
    // 2) xg_enc = emb @ Wih^T + bih + bhh  (TC)
    tc_gemm_nt<0><<<dim3(MTOK/128, G4H/128), 256, TC_SMEM>>>(
        p_A2, p_W2ih, enc_bih, enc_bhh, p_xg_enc, G4H, 1536);
    // 3) encoder LSTM: init + 512 sequential step launches
    enc_init_kernel<<<(BB*HH + 255)/256, 256>>>();
    for (int t = 0; t < TT; t++)
        enc_step_kernel<<<128, 256>>>(t, p_xg_enc, enc_Whh);
    // 4) xg_pos = henc @ pos_Wih^T + biases (fp32, small N)
    gemm_nt_kernel<0,true><<<dim3(1, MTOK/128), 256>>>(
        p_henc, pos_Wih, pos_bih, pos_bhh, p_xg_pos, MTOK, G4P, HH);
    // 5) pos LSTM + heads + mu scan
    pos_kernel<<<BB, 128>>>(pad_len, pos_Whh, W_mu, b_mu, W_sig, b_sig);
    // 6) attention weights
    attn_kernel<<<(BB*TT)/8, 256>>>(pad_len);
    // 7) ctx = g @ enc
    gemm_nn_kernel<<<dim3(HH/128, TT/128, BB), 256>>>(
        p_gw, p_henc, p_ctx, TT, HH, TT,
        (size_t)TT*TT, (size_t)TT*HH, (size_t)TT*HH);
    // 8) fused concat + A-split
    cat_split_kernel<<<(MTOK*256)/256, 256>>>();
    // 9) comb = tanh(cat @ W_cat^T + b_cat)  (TC, fp32 out)
    tc_gemm_nt<1><<<dim3(MTOK/128, HH/128), 256, TC_SMEM>>>(
        p_cat2, p_Wcat2, b_cat, nullptr, p_comb, HH, 3072);
    // 10) decoder: coalesced split of comb, then logits (TC, BM=BN=128)
    splitA_kernel<<<(MTOK*128)/256, 256>>>(p_comb, p_A2, HH);
    tc_gemm_nt<0><<<dim3(MTOK/128, VV/128), 256, TC_SMEM>>>(
        p_A2, p_B2, dec_b, nullptr, out, VV, 1536);

    (void)in_sizes; (void)n_in; (void)out_size;
}